// round 8
// baseline (speedup 1.0000x reference)
#include <cuda_runtime.h>

#define N_NODES 50000
#define N_EDGES 800000
#define D_IN 64
#define D_OUT 64
#define E_DIM 32
#define NK 96
#define BN_EPS 1e-5f

// tiles of 128 rows for node kernels
#define NT128 ((N_NODES + 127) / 128)   // 391
#define H_STRIDE 100                     // 96 + pad, 400B (16B-aligned rows)
#define O_STRIDE 68                      // 64 + pad, 272B (16B-aligned rows)

typedef unsigned long long ull;

#define FMA2(acc, a, b) \
    asm("fma.rn.f32x2 %0, %1, %2, %3;" : "=l"(acc) : "l"(a), "l"(b), "l"(acc))
#define PACK2(out, lo, hi) \
    asm("mov.b64 %0, {%1, %2};" : "=l"(out) : "f"(lo), "f"(hi))

// ---------------- scratch ----------------
__device__ __align__(16) float g_aggX[N_NODES * D_IN];
__device__ __align__(16) float g_aggE[N_NODES * E_DIM];
__device__ __align__(16) float g_deg[N_NODES];
__device__ __align__(16) float g_h[N_NODES * D_OUT];
__device__ __align__(16) float g_sum[D_OUT];
__device__ __align__(16) float g_sumsq[D_OUT];
__device__ __align__(16) float g_Wall[NK * D_OUT];   // rows 0..63: W1; rows 64..95: We@W1
__device__ __align__(16) float g_c2[D_OUT];          // be@W1
__device__ __align__(16) float g_scalef[D_OUT];
__device__ __align__(16) float g_shiftf[D_OUT];

// ---------------- kernel 0: zero ----------------
__global__ void zero_kernel() {
    int idx = blockIdx.x * blockDim.x + threadIdx.x;
    int stride = gridDim.x * blockDim.x;
    float4 z = make_float4(0.f, 0.f, 0.f, 0.f);
    for (int i = idx; i < N_NODES * (D_IN / 4); i += stride) ((float4*)g_aggX)[i] = z;
    for (int i = idx; i < N_NODES * (E_DIM / 4); i += stride) ((float4*)g_aggE)[i] = z;
    for (int i = idx; i < N_NODES; i += stride) g_deg[i] = 0.f;
    if (idx < D_OUT) { g_sum[idx] = 0.f; g_sumsq[idx] = 0.f; }
}

// ---------------- kernel 1: prep Wall = [W1 ; We@W1], c2 = be@W1 ---------------
__global__ void prep_kernel(const float* __restrict__ We,
                            const float* __restrict__ be,
                            const float* __restrict__ W1) {
    __shared__ float W1s[D_IN * D_OUT];
    int tid = threadIdx.x;
    for (int i = tid; i < D_IN * D_OUT; i += 256) W1s[i] = W1[i];
    __syncthreads();
    for (int i = tid; i < D_IN * D_OUT; i += 256) g_Wall[i] = W1s[i];
    for (int i = tid; i < E_DIM * D_OUT; i += 256) {
        int kk = i >> 6, d = i & 63;
        float s = 0.f;
        #pragma unroll 8
        for (int m = 0; m < D_IN; m++) s += We[kk * D_IN + m] * W1s[m * D_OUT + d];
        g_Wall[D_IN * D_OUT + i] = s;
    }
    if (tid < D_OUT) {
        float s = 0.f;
        #pragma unroll 8
        for (int m = 0; m < D_IN; m++) s += be[m] * W1s[m * D_OUT + tid];
        g_c2[tid] = s;
    }
}

// ---------------- kernel 2: edge scatter (R3-proven, unchanged) ----------------
__global__ void edge_kernel(const float4* __restrict__ x4,
                            const int* __restrict__ ei,
                            const float4* __restrict__ ea4) {
    int gwarp = (blockIdx.x * blockDim.x + threadIdx.x) >> 5;
    int lane = threadIdx.x & 31;
    int e0 = gwarp * 2;
    if (e0 >= N_EDGES) return;

    int half = lane >> 4, li = lane & 15;
    int e = e0 + half;
    bool v = (e < N_EDGES);
    int src = 0, dst = 0;
    if (v) {
        src = __ldg(&ei[e]);
        dst = __ldg(&ei[N_EDGES + e]);
    }
    if (v) {
        float4 xv = __ldg(&x4[(size_t)src * (D_IN / 4) + li]);
        atomicAdd(((float4*)(g_aggX + (size_t)dst * D_IN)) + li, xv);
    }
    int dA = __shfl_sync(0xffffffffu, dst, 0);
    int dB = __shfl_sync(0xffffffffu, dst, 16);
    if (lane < 16) {
        int e2 = e0 + (lane >> 3);
        if (e2 < N_EDGES) {
            int d2 = (lane < 8) ? dA : dB;
            int lj = lane & 7;
            float4 av = __ldg(&ea4[(size_t)e2 * (E_DIM / 4) + lj]);
            atomicAdd(((float4*)(g_aggE + (size_t)d2 * E_DIM)) + lj, av);
        }
    } else if (lane < 18) {
        int e3 = e0 + (lane - 16);
        if (e3 < N_EDGES) atomicAdd(&g_deg[(lane == 16) ? dA : dB], 1.f);
    }
}

// ---------------- kernel 3: node_h, row-per-lane, packed f32x2 -----------------
// Block: 256 thr = 8 warps; block handles 128 rows (4 tiles of 32).
// Warp w -> tile w>>1, d-half (w&1)*32. Lane owns row (tile*32+lane), 16 packed
// d-pair accumulators. Dynamic smem: Ws[96*64] + stS[4][32*H_STRIDE].
__global__ __launch_bounds__(256) void node_h_kernel(const float* __restrict__ x,
                                                     const float* __restrict__ b1) {
    extern __shared__ __align__(16) float smem[];
    float* Ws  = smem;                     // 6144 floats
    float* stS = smem + NK * D_OUT;        // 4*32*100 = 12800 floats
    __shared__ __align__(16) float c2s[D_OUT];
    __shared__ __align__(16) float b1s[D_OUT];

    int tid = threadIdx.x;
    for (int i = tid; i < NK * D_OUT / 4; i += 256)
        ((float4*)Ws)[i] = ((const float4*)g_Wall)[i];
    if (tid < D_OUT) { c2s[tid] = g_c2[tid]; b1s[tid] = b1[tid]; }

    int rowBase = blockIdx.x * 128;
    // ---- stage 128 rows x 96 floats, row-major stride 100 ----
    {
        int rr = tid >> 1;                 // 0..127
        int half = tid & 1;
        int row = rowBase + rr;
        float* dstRow = stS + (rr >> 5) * (32 * H_STRIDE) + (rr & 31) * H_STRIDE;
        if (row < N_NODES) {
            if (half == 0) {
                #pragma unroll
                for (int c = 0; c < 12; c++) {
                    float4 a = ((const float4*)g_aggX)[row * 16 + c];
                    float4 xv = __ldg(&((const float4*)x)[row * 16 + c]);
                    *(float4*)(dstRow + c * 4) =
                        make_float4(a.x + xv.x, a.y + xv.y, a.z + xv.z, a.w + xv.w);
                }
            } else {
                #pragma unroll
                for (int c = 12; c < 16; c++) {
                    float4 a = ((const float4*)g_aggX)[row * 16 + c];
                    float4 xv = __ldg(&((const float4*)x)[row * 16 + c]);
                    *(float4*)(dstRow + c * 4) =
                        make_float4(a.x + xv.x, a.y + xv.y, a.z + xv.z, a.w + xv.w);
                }
                #pragma unroll
                for (int c = 0; c < 8; c++)
                    *(float4*)(dstRow + 64 + c * 4) = ((const float4*)g_aggE)[row * 8 + c];
            }
        } else {
            float4 z = make_float4(0.f, 0.f, 0.f, 0.f);
            if (half == 0) {
                #pragma unroll
                for (int c = 0; c < 12; c++) *(float4*)(dstRow + c * 4) = z;
            } else {
                #pragma unroll
                for (int c = 12; c < 24; c++) *(float4*)(dstRow + c * 4) = z;
            }
        }
    }
    __syncthreads();

    // ---- compute ----
    int w = tid >> 5, lane = tid & 31;
    int tile = w >> 1, d0 = (w & 1) * 32;
    int row = rowBase + tile * 32 + lane;
    float deg = (row < N_NODES) ? g_deg[row] : 0.f;
    ull deg2; PACK2(deg2, deg, deg);

    ull acc[16];
    {
        const ull* c2p = (const ull*)(c2s + d0);
        const ull* b1p = (const ull*)(b1s + d0);
        #pragma unroll
        for (int i = 0; i < 16; i++) { acc[i] = b1p[i]; FMA2(acc[i], deg2, c2p[i]); }
    }

    const float* arow = stS + tile * (32 * H_STRIDE) + lane * H_STRIDE;
    #pragma unroll 4
    for (int k4 = 0; k4 < NK / 4; k4++) {
        float4 a4 = *(const float4*)(arow + k4 * 4);
        float av[4] = {a4.x, a4.y, a4.z, a4.w};
        #pragma unroll
        for (int j = 0; j < 4; j++) {
            ull a2; PACK2(a2, av[j], av[j]);
            const ulonglong2* wp = (const ulonglong2*)(Ws + (k4 * 4 + j) * D_OUT + d0);
            #pragma unroll
            for (int q = 0; q < 8; q++) {
                ulonglong2 ww = wp[q];
                FMA2(acc[2 * q], a2, ww.x);
                FMA2(acc[2 * q + 1], a2, ww.y);
            }
        }
    }

    if (row < N_NODES) {
        ulonglong2* hrow = (ulonglong2*)(g_h + (size_t)row * 64 + d0);
        #pragma unroll
        for (int q = 0; q < 8; q++) {
            ulonglong2 v; v.x = acc[2 * q]; v.y = acc[2 * q + 1];
            hrow[q] = v;
        }
    }
}

// ---------------- kernel 4: bn stats over g_h ----------------
__global__ void bn_stats_kernel() {
    __shared__ float sArr[D_OUT], qArr[D_OUT];
    int tid = threadIdx.x;
    if (tid < D_OUT) { sArr[tid] = 0.f; qArr[tid] = 0.f; }
    __syncthreads();
    int d = tid & 63;
    float s = 0.f, q = 0.f;
    int total = N_NODES * D_OUT;
    int stride = gridDim.x * blockDim.x;
    for (int i = blockIdx.x * blockDim.x + tid; i < total; i += stride) {
        float v = g_h[i];
        s += v; q += v * v;
    }
    atomicAdd(&sArr[d], s);
    atomicAdd(&qArr[d], q);
    __syncthreads();
    if (tid < D_OUT) {
        atomicAdd(&g_sum[tid], sArr[tid]);
        atomicAdd(&g_sumsq[tid], qArr[tid]);
    }
}

// ---------------- kernel 5: bn finalize ----------------
__global__ void bn_kernel(const float* __restrict__ gamma,
                          const float* __restrict__ beta) {
    int d = threadIdx.x;   // 64
    float n = (float)N_NODES;
    float mean = g_sum[d] / n;
    float var = g_sumsq[d] / n - mean * mean;
    float rstd = rsqrtf(var + BN_EPS);
    float sc = gamma[d] * rstd;
    g_scalef[d] = sc;
    g_shiftf[d] = beta[d] - mean * sc;
}

// ---------------- kernel 6: node_out, row-per-lane ----------------
__global__ __launch_bounds__(256) void node_out_kernel(const float* __restrict__ W2,
                                                       const float* __restrict__ b2,
                                                       float* __restrict__ out) {
    extern __shared__ __align__(16) float smem[];
    float* Ws  = smem;                       // 4096 floats
    float* stS = smem + D_OUT * D_OUT;       // 4*32*68 = 8704 floats
    __shared__ __align__(16) float scf[D_OUT], shf[D_OUT];

    int tid = threadIdx.x;
    for (int i = tid; i < D_OUT * D_OUT / 4; i += 256)
        ((float4*)Ws)[i] = __ldg(&((const float4*)W2)[i]);
    if (tid < D_OUT) { scf[tid] = g_scalef[tid]; shf[tid] = g_shiftf[tid]; }
    __syncthreads();

    int rowBase = blockIdx.x * 128;
    // ---- stage relu(bn(h)) : 128 rows x 64 floats, stride 68 ----
    {
        int rr = tid >> 1;
        int half = tid & 1;
        int row = rowBase + rr;
        float* dstRow = stS + (rr >> 5) * (32 * O_STRIDE) + (rr & 31) * O_STRIDE;
        #pragma unroll
        for (int c0 = 0; c0 < 8; c0++) {
            int c = half * 8 + c0;
            float4 v = make_float4(0.f, 0.f, 0.f, 0.f);
            if (row < N_NODES) {
                float4 hv = ((const float4*)g_h)[(size_t)row * 16 + c];
                float4 sc = ((const float4*)scf)[c];
                float4 sh = ((const float4*)shf)[c];
                v.x = fmaxf(0.f, hv.x * sc.x + sh.x);
                v.y = fmaxf(0.f, hv.y * sc.y + sh.y);
                v.z = fmaxf(0.f, hv.z * sc.z + sh.z);
                v.w = fmaxf(0.f, hv.w * sc.w + sh.w);
            }
            *(float4*)(dstRow + c * 4) = v;
        }
    }
    __syncthreads();

    int w = tid >> 5, lane = tid & 31;
    int tile = w >> 1, d0 = (w & 1) * 32;
    int row = rowBase + tile * 32 + lane;

    ull acc[16];
    {
        const ull* b2p = (const ull*)(b2 + d0);
        #pragma unroll
        for (int i = 0; i < 16; i++) acc[i] = __ldg(&b2p[i]);
    }

    const float* arow = stS + tile * (32 * O_STRIDE) + lane * O_STRIDE;
    #pragma unroll 4
    for (int k4 = 0; k4 < D_OUT / 4; k4++) {
        float4 a4 = *(const float4*)(arow + k4 * 4);
        float av[4] = {a4.x, a4.y, a4.z, a4.w};
        #pragma unroll
        for (int j = 0; j < 4; j++) {
            ull a2; PACK2(a2, av[j], av[j]);
            const ulonglong2* wp = (const ulonglong2*)(Ws + (k4 * 4 + j) * D_OUT + d0);
            #pragma unroll
            for (int q = 0; q < 8; q++) {
                ulonglong2 ww = wp[q];
                FMA2(acc[2 * q], a2, ww.x);
                FMA2(acc[2 * q + 1], a2, ww.y);
            }
        }
    }

    if (row < N_NODES) {
        ulonglong2* orow = (ulonglong2*)(out + (size_t)row * 64 + d0);
        #pragma unroll
        for (int q = 0; q < 8; q++) {
            ulonglong2 v; v.x = acc[2 * q]; v.y = acc[2 * q + 1];
            orow[q] = v;
        }
    }
}

// ---------------- launch ----------------
extern "C" void kernel_launch(void* const* d_in, const int* in_sizes, int n_in,
                              void* d_out, int out_size) {
    const float* x     = (const float*)d_in[0];
    const int* ei      = (const int*)d_in[1];
    const float* ea    = (const float*)d_in[2];
    const float* We    = (const float*)d_in[3];
    const float* be    = (const float*)d_in[4];
    const float* W1    = (const float*)d_in[5];
    const float* b1    = (const float*)d_in[6];
    const float* gamma = (const float*)d_in[7];
    const float* beta  = (const float*)d_in[8];
    const float* W2    = (const float*)d_in[9];
    const float* b2    = (const float*)d_in[10];
    float* out         = (float*)d_out;

    const int smemH = (NK * D_OUT + 4 * 32 * H_STRIDE) * sizeof(float);   // 75776
    const int smemO = (D_OUT * D_OUT + 4 * 32 * O_STRIDE) * sizeof(float); // 51200
    cudaFuncSetAttribute(node_h_kernel, cudaFuncAttributeMaxDynamicSharedMemorySize, smemH);
    cudaFuncSetAttribute(node_out_kernel, cudaFuncAttributeMaxDynamicSharedMemorySize, smemO);

    zero_kernel<<<2048, 256>>>();
    prep_kernel<<<1, 256>>>(We, be, W1);

    int nWarps = (N_EDGES + 1) / 2;
    int nBlocks = (nWarps + 7) / 8;
    edge_kernel<<<nBlocks, 256>>>((const float4*)x, ei, (const float4*)ea);

    node_h_kernel<<<NT128, 256, smemH>>>(x, b1);
    bn_stats_kernel<<<296, 256>>>();
    bn_kernel<<<1, 64>>>(gamma, beta);
    node_out_kernel<<<NT128, 256, smemO>>>(W2, b2, out);
}